// round 9
// baseline (speedup 1.0000x reference)
#include <cuda_runtime.h>

#define B_      2
#define CIN     64
#define HIN     128
#define WIN     256
#define COUT    64
#define KK      9
#define HOUT    128
#define WOUT    256
#define HW      (HIN * WIN)     // 32768
#define HWO     (HOUT * WOUT)   // 32768
#define NTHREADS 128
#define SROW    68              // sample row stride in floats (16B-aligned, bank-spreading)

#define SMP_BUF (CIN * SROW)            // 4352 floats
#define W_BUF   (CIN * COUT)            // 4096 floats
#define SMEM_FLOATS (2 * SMP_BUF + 2 * W_BUF)
#define SMEM_BYTES  (SMEM_FLOATS * 4)   // 67584 B -> dynamic smem, 3 CTAs/SM

// Scratch (no allocation allowed)
__device__ float g_wT[KK * CIN * COUT];                 // wT[k][c][o]
__device__ float g_xT[(size_t)B_ * HW * CIN];           // xT[b][pos][c]  16.8 MB (L2-resident)

__global__ void transpose_weight_kernel(const float* __restrict__ w) {
    int idx = blockIdx.x * blockDim.x + threadIdx.x;
    if (idx < COUT * CIN * KK) {
        int k = idx % KK;
        int c = (idx / KK) % CIN;
        int o = idx / (KK * CIN);
        g_wT[(k * CIN + c) * COUT + o] = w[idx];
    }
}

// xT[b][pos][c] = x[b][c][pos]; tiles of 64 ch x 32 pos, both phases coalesced
__global__ __launch_bounds__(256) void transpose_x_kernel(const float* __restrict__ x) {
    __shared__ float t[CIN][33];
    const int tid  = threadIdx.x;
    const int pos0 = blockIdx.x * 32;
    const int b    = blockIdx.y;
    {
        const int pl = tid & 31;
        const int c0 = tid >> 5;
#pragma unroll
        for (int i = 0; i < 8; i++) {
            const int c = c0 + i * 8;
            t[c][pl] = x[((size_t)b * CIN + c) * HW + pos0 + pl];
        }
    }
    __syncthreads();
    {
        const int c  = tid & 63;
        const int p0 = tid >> 6;
#pragma unroll
        for (int i = 0; i < 8; i++) {
            const int p = p0 + i * 4;
            g_xT[((size_t)b * HW + pos0 + p) * CIN + c] = t[c][p];
        }
    }
}

// ---- packed fp32x2 helpers ----
__device__ __forceinline__ unsigned long long pack2(float a, float b) {
    unsigned long long r;
    asm("mov.b64 %0, {%1, %2};" : "=l"(r) : "f"(a), "f"(b));
    return r;
}
__device__ __forceinline__ void fma2(unsigned long long& d,
                                     unsigned long long a,
                                     unsigned long long b) {
    asm("fma.rn.f32x2 %0, %1, %2, %0;" : "+l"(d) : "l"(a), "l"(b));
}
__device__ __forceinline__ void unpack2(unsigned long long v, float& a, float& b) {
    asm("mov.b64 {%0, %1}, %2;" : "=f"(a), "=f"(b) : "l"(v));
}

// stage weights wT[k] -> sw (coalesced float4)
__device__ __forceinline__ void stage_w(int k, float* __restrict__ sw, int tid) {
    const float4* src = reinterpret_cast<const float4*>(g_wT + k * CIN * COUT);
    float4* dst = reinterpret_cast<float4*>(sw);
#pragma unroll
    for (int i = 0; i < 8; i++)
        dst[i * NTHREADS + tid] = src[i * NTHREADS + tid];
}

// deformable bilinear sampling for kernel-tap k into smp (swizzled transposed layout)
__device__ __forceinline__ void do_sample(int k, float* __restrict__ smp,
                                          const float* __restrict__ xTb,
                                          const float* __restrict__ offset,
                                          int b, int h, int w_base,
                                          int warp, int half, int cl) {
    const int ki = k / 3, kj = k - 3 * ki;
#pragma unroll
    for (int it = 0; it < 8; it++) {
        const int p     = it * 8 + warp * 2 + half;   // 0..63, each exactly once
        const int w_out = w_base + p;

        const float offy = __ldg(offset + ((size_t)(b * KK + k) * 2 + 0) * HWO + h * WOUT + w_out);
        const float offx = __ldg(offset + ((size_t)(b * KK + k) * 2 + 1) * HWO + h * WOUT + w_out);
        const float py = (float)(h - 1 + ki) + offy;
        const float px = (float)(w_out - 1 + kj) + offx;
        const float y0f = floorf(py), x0f = floorf(px);
        const float wy = py - y0f, wx = px - x0f;
        const int y0 = (int)y0f, x0 = (int)x0f;
        const int y1 = y0 + 1, x1 = x0 + 1;
        const bool vy0 = (y0 >= 0) & (y0 < HIN);
        const bool vy1 = (y1 >= 0) & (y1 < HIN);
        const bool vx0 = (x0 >= 0) & (x0 < WIN);
        const bool vx1 = (x1 >= 0) & (x1 < WIN);

        float w00 = (1.f - wy) * (1.f - wx);
        float w01 = (1.f - wy) * wx;
        float w10 = wy * (1.f - wx);
        float w11 = wy * wx;
        if (!(vy0 && vx0)) w00 = 0.f;
        if (!(vy0 && vx1)) w01 = 0.f;
        if (!(vy1 && vx0)) w10 = 0.f;
        if (!(vy1 && vx1)) w11 = 0.f;

        const int y0c = min(max(y0, 0), HIN - 1);
        const int y1c = min(max(y1, 0), HIN - 1);
        const int x0c = min(max(x0, 0), WIN - 1);
        const int x1c = min(max(x1, 0), WIN - 1);

        const int cofs = cl * 4;
        const float4 v00 = *reinterpret_cast<const float4*>(xTb + ((size_t)(y0c * WIN + x0c)) * CIN + cofs);
        const float4 v01 = *reinterpret_cast<const float4*>(xTb + ((size_t)(y0c * WIN + x1c)) * CIN + cofs);
        const float4 v10 = *reinterpret_cast<const float4*>(xTb + ((size_t)(y1c * WIN + x0c)) * CIN + cofs);
        const float4 v11 = *reinterpret_cast<const float4*>(xTb + ((size_t)(y1c * WIN + x1c)) * CIN + cofs);

        float4 r;
        r.x = w00 * v00.x + w01 * v01.x + w10 * v10.x + w11 * v11.x;
        r.y = w00 * v00.y + w01 * v01.y + w10 * v10.y + w11 * v11.y;
        r.z = w00 * v00.z + w01 * v01.z + w10 * v10.z + w11 * v11.z;
        r.w = w00 * v00.w + w01 * v01.w + w10 * v10.w + w11 * v11.w;

        // swizzled transposed store: element (c,p) at word c*SROW + 4*((p>>2)^(c>>2 & 7)) + (p&3)
        const int wofs = ((p >> 2) ^ (cl & 7)) * 4 + (p & 3);
        smp[(cofs + 0) * SROW + wofs] = r.x;
        smp[(cofs + 1) * SROW + wofs] = r.y;
        smp[(cofs + 2) * SROW + wofs] = r.z;
        smp[(cofs + 3) * SROW + wofs] = r.w;
    }
}

// GEMM: acc[o][p] += W[c][o] * s[c][p]   (packed f32x2 over o-pairs)
__device__ __forceinline__ void do_gemm(const float* __restrict__ smp,
                                        const float* __restrict__ sw,
                                        unsigned long long acc2[4][4],
                                        int og, int pg) {
#pragma unroll 32
    for (int c = 0; c < CIN; c++) {
        const int swz = (c >> 2) & 7;   // const-folded under unroll
        const float4 sv = *reinterpret_cast<const float4*>(smp + c * SROW + ((pg ^ swz) << 2));
        const ulonglong2 wp01 = *reinterpret_cast<const ulonglong2*>(sw + c * COUT + (og << 3));
        const ulonglong2 wp23 = *reinterpret_cast<const ulonglong2*>(sw + c * COUT + (og << 3) + 4);

        const unsigned long long s0 = pack2(sv.x, sv.x);
        const unsigned long long s1 = pack2(sv.y, sv.y);
        const unsigned long long s2 = pack2(sv.z, sv.z);
        const unsigned long long s3 = pack2(sv.w, sv.w);

        fma2(acc2[0][0], wp01.x, s0); fma2(acc2[0][1], wp01.x, s1);
        fma2(acc2[0][2], wp01.x, s2); fma2(acc2[0][3], wp01.x, s3);
        fma2(acc2[1][0], wp01.y, s0); fma2(acc2[1][1], wp01.y, s1);
        fma2(acc2[1][2], wp01.y, s2); fma2(acc2[1][3], wp01.y, s3);
        fma2(acc2[2][0], wp23.x, s0); fma2(acc2[2][1], wp23.x, s1);
        fma2(acc2[2][2], wp23.x, s2); fma2(acc2[2][3], wp23.x, s3);
        fma2(acc2[3][0], wp23.y, s0); fma2(acc2[3][1], wp23.y, s1);
        fma2(acc2[3][2], wp23.y, s2); fma2(acc2[3][3], wp23.y, s3);
    }
}

__global__ __launch_bounds__(NTHREADS) void deform_conv_kernel(
    const float* __restrict__ offset,
    const float* __restrict__ bias,
    float* __restrict__ out)
{
    extern __shared__ __align__(16) float smem[];
    // layout: [smp buf0][smp buf1][w buf0][w buf1]
    float* smp_buf[2] = { smem, smem + SMP_BUF };
    float* w_buf[2]   = { smem + 2 * SMP_BUF, smem + 2 * SMP_BUF + W_BUF };

    const int tid    = threadIdx.x;
    const int wtile  = blockIdx.x;   // 0..3
    const int h      = blockIdx.y;   // 0..127
    const int b      = blockIdx.z;   // 0..1
    const int w_base = wtile * 64;

    const int warp = tid >> 5;
    const int lane = tid & 31;
    const int half = lane >> 4;
    const int cl   = lane & 15;

    const int og = tid & 7;
    const int pg = tid >> 3;

    const float* xTb = g_xT + (size_t)b * HW * CIN;

    unsigned long long acc2[4][4];
#pragma unroll
    for (int j = 0; j < 4; j++)
#pragma unroll
        for (int p = 0; p < 4; p++) acc2[j][p] = 0ULL;

    // prologue: fill buffer 0 for k=0
    stage_w(0, w_buf[0], tid);
    do_sample(0, smp_buf[0], xTb, offset, b, h, w_base, warp, half, cl);
    __syncthreads();

    // pipelined mainloop: one sync per iteration
    for (int k = 0; k < KK; k++) {
        const int cur = k & 1;
        if (k + 1 < KK) {
            const int nxt = cur ^ 1;
            stage_w(k + 1, w_buf[nxt], tid);
            do_sample(k + 1, smp_buf[nxt], xTb, offset, b, h, w_base, warp, half, cl);
        }
        do_gemm(smp_buf[cur], w_buf[cur], acc2, og, pg);
        __syncthreads();   // buf[cur] free for k+2 writes; buf[nxt] ready for k+1 reads
    }

    // epilogue: unpack, add bias, float4 stores
    float vals[8][4];
#pragma unroll
    for (int j = 0; j < 4; j++)
#pragma unroll
        for (int p = 0; p < 4; p++)
            unpack2(acc2[j][p], vals[2 * j][p], vals[2 * j + 1][p]);

#pragma unroll
    for (int i = 0; i < 8; i++) {
        const int o = (og << 3) + i;
        const float bv = __ldg(bias + o);
        float4 r = make_float4(vals[i][0] + bv, vals[i][1] + bv,
                               vals[i][2] + bv, vals[i][3] + bv);
        *reinterpret_cast<float4*>(
            out + (((size_t)b * COUT + o) * HOUT + h) * WOUT + w_base + (pg << 2)) = r;
    }
}

extern "C" void kernel_launch(void* const* d_in, const int* in_sizes, int n_in,
                              void* d_out, int out_size)
{
    const float* x      = (const float*)d_in[0];
    const float* offset = (const float*)d_in[1];
    const float* weight = (const float*)d_in[2];
    const float* bias   = (const float*)d_in[3];
    float* out          = (float*)d_out;

    cudaFuncSetAttribute(deform_conv_kernel,
                         cudaFuncAttributeMaxDynamicSharedMemorySize, SMEM_BYTES);

    transpose_weight_kernel<<<(COUT * CIN * KK + 255) / 256, 256>>>(weight);

    dim3 gx(HW / 32, B_);
    transpose_x_kernel<<<gx, 256>>>(x);

    dim3 grid(WOUT / 64, HOUT, B_);
    deform_conv_kernel<<<grid, NTHREADS, SMEM_BYTES>>>(offset, bias, out);
}

// round 13
// speedup vs baseline: 1.1112x; 1.1112x over previous
#include <cuda_runtime.h>

#define B_      2
#define CIN     64
#define HIN     128
#define WIN     256
#define COUT    64
#define KK      9
#define HOUT    128
#define WOUT    256
#define HW      (HIN * WIN)     // 32768
#define HWO     (HOUT * WOUT)   // 32768
#define NTHREADS 128
#define SROW    68              // sample row stride in floats

#define SMP_BUF (CIN * SROW)            // 4352 floats
#define W_BUF   (CIN * COUT)            // 4096 floats
#define SMEM_FLOATS (2 * SMP_BUF + 2 * W_BUF)
#define SMEM_BYTES  (SMEM_FLOATS * 4)   // 67584 B dynamic

// Scratch (no allocation allowed)
__device__ float g_wT[KK * CIN * COUT];                 // wT[k][c][o]
__device__ float g_xT[(size_t)B_ * HW * CIN];           // xT[b][pos][c]  16.8 MB (L2-resident)

__global__ void transpose_weight_kernel(const float* __restrict__ w) {
    int idx = blockIdx.x * blockDim.x + threadIdx.x;
    if (idx < COUT * CIN * KK) {
        int k = idx % KK;
        int c = (idx / KK) % CIN;
        int o = idx / (KK * CIN);
        g_wT[(k * CIN + c) * COUT + o] = w[idx];
    }
}

__global__ __launch_bounds__(256) void transpose_x_kernel(const float* __restrict__ x) {
    __shared__ float t[CIN][33];
    const int tid  = threadIdx.x;
    const int pos0 = blockIdx.x * 32;
    const int b    = blockIdx.y;
    {
        const int pl = tid & 31;
        const int c0 = tid >> 5;
#pragma unroll
        for (int i = 0; i < 8; i++) {
            const int c = c0 + i * 8;
            t[c][pl] = x[((size_t)b * CIN + c) * HW + pos0 + pl];
        }
    }
    __syncthreads();
    {
        const int c  = tid & 63;
        const int p0 = tid >> 6;
#pragma unroll
        for (int i = 0; i < 8; i++) {
            const int p = p0 + i * 4;
            g_xT[((size_t)b * HW + pos0 + p) * CIN + c] = t[c][p];
        }
    }
}

// ---- packed fp32x2 helpers ----
__device__ __forceinline__ unsigned long long pack2(float a, float b) {
    unsigned long long r;
    asm("mov.b64 %0, {%1, %2};" : "=l"(r) : "f"(a), "f"(b));
    return r;
}
__device__ __forceinline__ void fma2(unsigned long long& d,
                                     unsigned long long a,
                                     unsigned long long b) {
    asm("fma.rn.f32x2 %0, %1, %2, %0;" : "+l"(d) : "l"(a), "l"(b));
}
__device__ __forceinline__ void unpack2(unsigned long long v, float& a, float& b) {
    asm("mov.b64 {%0, %1}, %2;" : "=f"(a), "=f"(b) : "l"(v));
}

__device__ __forceinline__ void stage_w(int k, float* __restrict__ sw, int tid) {
    const float4* src = reinterpret_cast<const float4*>(g_wT + k * CIN * COUT);
    float4* dst = reinterpret_cast<float4*>(sw);
#pragma unroll
    for (int i = 0; i < 8; i++)
        dst[i * NTHREADS + tid] = src[i * NTHREADS + tid];
}

// full (non-pipelined) sampling, used in prologue only
__device__ __forceinline__ void do_sample_full(int k, float* __restrict__ smp,
                                               const float* __restrict__ xTb,
                                               const float* __restrict__ offset,
                                               int b, int h, int w_base,
                                               int warp, int half, int cl) {
    const int ki = k / 3, kj = k - 3 * ki;
#pragma unroll
    for (int it = 0; it < 8; it++) {
        const int p     = it * 8 + warp * 2 + half;
        const int w_out = w_base + p;

        const float offy = __ldg(offset + ((size_t)(b * KK + k) * 2 + 0) * HWO + h * WOUT + w_out);
        const float offx = __ldg(offset + ((size_t)(b * KK + k) * 2 + 1) * HWO + h * WOUT + w_out);
        const float py = (float)(h - 1 + ki) + offy;
        const float px = (float)(w_out - 1 + kj) + offx;
        const float y0f = floorf(py), x0f = floorf(px);
        const float wy = py - y0f, wx = px - x0f;
        const int y0 = (int)y0f, x0 = (int)x0f;
        const int y1 = y0 + 1, x1 = x0 + 1;
        const bool vy0 = (y0 >= 0) & (y0 < HIN);
        const bool vy1 = (y1 >= 0) & (y1 < HIN);
        const bool vx0 = (x0 >= 0) & (x0 < WIN);
        const bool vx1 = (x1 >= 0) & (x1 < WIN);

        float w00 = (1.f - wy) * (1.f - wx);
        float w01 = (1.f - wy) * wx;
        float w10 = wy * (1.f - wx);
        float w11 = wy * wx;
        if (!(vy0 && vx0)) w00 = 0.f;
        if (!(vy0 && vx1)) w01 = 0.f;
        if (!(vy1 && vx0)) w10 = 0.f;
        if (!(vy1 && vx1)) w11 = 0.f;

        const int y0c = min(max(y0, 0), HIN - 1);
        const int y1c = min(max(y1, 0), HIN - 1);
        const int x0c = min(max(x0, 0), WIN - 1);
        const int x1c = min(max(x1, 0), WIN - 1);

        const int cofs = cl * 4;
        const float4 v00 = *reinterpret_cast<const float4*>(xTb + ((size_t)(y0c * WIN + x0c)) * CIN + cofs);
        const float4 v01 = *reinterpret_cast<const float4*>(xTb + ((size_t)(y0c * WIN + x1c)) * CIN + cofs);
        const float4 v10 = *reinterpret_cast<const float4*>(xTb + ((size_t)(y1c * WIN + x0c)) * CIN + cofs);
        const float4 v11 = *reinterpret_cast<const float4*>(xTb + ((size_t)(y1c * WIN + x1c)) * CIN + cofs);

        float4 r;
        r.x = w00 * v00.x + w01 * v01.x + w10 * v10.x + w11 * v11.x;
        r.y = w00 * v00.y + w01 * v01.y + w10 * v10.y + w11 * v11.y;
        r.z = w00 * v00.z + w01 * v01.z + w10 * v10.z + w11 * v11.z;
        r.w = w00 * v00.w + w01 * v01.w + w10 * v10.w + w11 * v11.w;

        const int wofs = ((p >> 2) ^ (cl & 7)) * 4 + (p & 3);
        smp[(cofs + 0) * SROW + wofs] = r.x;
        smp[(cofs + 1) * SROW + wofs] = r.y;
        smp[(cofs + 2) * SROW + wofs] = r.z;
        smp[(cofs + 3) * SROW + wofs] = r.w;
    }
}

// one 8-c GEMM chunk; c0 must be compile-time (call from unrolled loop)
__device__ __forceinline__ void gemm_chunk(const float* __restrict__ smp,
                                           const float* __restrict__ sw,
                                           unsigned long long acc2[4][4],
                                           int og, int pg, int c0) {
#pragma unroll
    for (int cc = 0; cc < 8; cc++) {
        const int c = c0 + cc;
        const int swz = (c >> 2) & 7;
        const float4 sv = *reinterpret_cast<const float4*>(smp + c * SROW + ((pg ^ swz) << 2));
        const ulonglong2 wp01 = *reinterpret_cast<const ulonglong2*>(sw + c * COUT + (og << 3));
        const ulonglong2 wp23 = *reinterpret_cast<const ulonglong2*>(sw + c * COUT + (og << 3) + 4);

        const unsigned long long s0 = pack2(sv.x, sv.x);
        const unsigned long long s1 = pack2(sv.y, sv.y);
        const unsigned long long s2 = pack2(sv.z, sv.z);
        const unsigned long long s3 = pack2(sv.w, sv.w);

        fma2(acc2[0][0], wp01.x, s0); fma2(acc2[0][1], wp01.x, s1);
        fma2(acc2[0][2], wp01.x, s2); fma2(acc2[0][3], wp01.x, s3);
        fma2(acc2[1][0], wp01.y, s0); fma2(acc2[1][1], wp01.y, s1);
        fma2(acc2[1][2], wp01.y, s2); fma2(acc2[1][3], wp01.y, s3);
        fma2(acc2[2][0], wp23.x, s0); fma2(acc2[2][1], wp23.x, s1);
        fma2(acc2[2][2], wp23.x, s2); fma2(acc2[2][3], wp23.x, s3);
        fma2(acc2[3][0], wp23.y, s0); fma2(acc2[3][1], wp23.y, s1);
        fma2(acc2[3][2], wp23.y, s2); fma2(acc2[3][3], wp23.y, s3);
    }
}

__global__ __launch_bounds__(NTHREADS) void deform_conv_kernel(
    const float* __restrict__ offset,
    const float* __restrict__ bias,
    float* __restrict__ out)
{
    extern __shared__ __align__(16) float smem[];
    float* smp_buf[2] = { smem, smem + SMP_BUF };
    float* w_buf[2]   = { smem + 2 * SMP_BUF, smem + 2 * SMP_BUF + W_BUF };

    const int tid    = threadIdx.x;
    const int wtile  = blockIdx.x;
    const int h      = blockIdx.y;
    const int b      = blockIdx.z;
    const int w_base = wtile * 64;

    const int warp = tid >> 5;
    const int lane = tid & 31;
    const int half = lane >> 4;
    const int cl   = lane & 15;
    const int cofs = cl * 4;

    const int og = tid & 7;
    const int pg = tid >> 3;

    const float* xTb = g_xT + (size_t)b * HW * CIN;
    const float* off_b = offset + (size_t)b * KK * 2 * HWO + h * WOUT + w_base;

    unsigned long long acc2[4][4];
#pragma unroll
    for (int j = 0; j < 4; j++)
#pragma unroll
        for (int p = 0; p < 4; p++) acc2[j][p] = 0ULL;

    // prologue: buffer 0 holds k=0 data
    stage_w(0, w_buf[0], tid);
    do_sample_full(0, smp_buf[0], xTb, offset, b, h, w_base, warp, half, cl);
    __syncthreads();

    for (int k = 0; k < KK; k++) {
        const int cur = k & 1;
        const int nxt = cur ^ 1;
        const bool pf = (k + 1 < KK);
        const int kn = pf ? (k + 1) : k;       // safe dummy when !pf
        const int kni = kn / 3, knj = kn - 3 * kni;

        if (pf) stage_w(kn, w_buf[nxt], tid);

        // prefetch offsets for sampling iter 0 of k+1
        float offy_n = 0.f, offx_n = 0.f;
        {
            const int p0 = warp * 2 + half;
            if (pf) {
                offy_n = __ldg(off_b + ((size_t)kn * 2 + 0) * HWO + p0);
                offx_n = __ldg(off_b + ((size_t)kn * 2 + 1) * HWO + p0);
            }
        }

#pragma unroll
        for (int i = 0; i < 8; i++) {
            // ---- (a) from offsets: addresses + issue corner loads for iter i of k+1
            const int p     = i * 8 + warp * 2 + half;
            const int w_out = w_base + p;
            float w00 = 0.f, w01 = 0.f, w10 = 0.f, w11 = 0.f;
            float4 v00, v01, v10, v11;
            int wofs = 0;
            if (pf) {
                const float py = (float)(h - 1 + kni) + offy_n;
                const float px = (float)(w_out - 1 + knj) + offx_n;
                const float y0f = floorf(py), x0f = floorf(px);
                const float wy = py - y0f, wx = px - x0f;
                const int y0 = (int)y0f, x0 = (int)x0f;
                const int y1 = y0 + 1, x1 = x0 + 1;
                const bool vy0 = (y0 >= 0) & (y0 < HIN);
                const bool vy1 = (y1 >= 0) & (y1 < HIN);
                const bool vx0 = (x0 >= 0) & (x0 < WIN);
                const bool vx1 = (x1 >= 0) & (x1 < WIN);

                w00 = (1.f - wy) * (1.f - wx);
                w01 = (1.f - wy) * wx;
                w10 = wy * (1.f - wx);
                w11 = wy * wx;
                if (!(vy0 && vx0)) w00 = 0.f;
                if (!(vy0 && vx1)) w01 = 0.f;
                if (!(vy1 && vx0)) w10 = 0.f;
                if (!(vy1 && vx1)) w11 = 0.f;

                const int y0c = min(max(y0, 0), HIN - 1);
                const int y1c = min(max(y1, 0), HIN - 1);
                const int x0c = min(max(x0, 0), WIN - 1);
                const int x1c = min(max(x1, 0), WIN - 1);

                v00 = *reinterpret_cast<const float4*>(xTb + ((size_t)(y0c * WIN + x0c)) * CIN + cofs);
                v01 = *reinterpret_cast<const float4*>(xTb + ((size_t)(y0c * WIN + x1c)) * CIN + cofs);
                v10 = *reinterpret_cast<const float4*>(xTb + ((size_t)(y1c * WIN + x0c)) * CIN + cofs);
                v11 = *reinterpret_cast<const float4*>(xTb + ((size_t)(y1c * WIN + x1c)) * CIN + cofs);

                wofs = ((p >> 2) ^ (cl & 7)) * 4 + (p & 3);

                // ---- (b) prefetch offsets for iter i+1
                if (i < 7) {
                    const int pn = (i + 1) * 8 + warp * 2 + half;
                    offy_n = __ldg(off_b + ((size_t)kn * 2 + 0) * HWO + pn);
                    offx_n = __ldg(off_b + ((size_t)kn * 2 + 1) * HWO + pn);
                }
            }

            // ---- (c) GEMM chunk i of k — covers the corner-load latency
            gemm_chunk(smp_buf[cur], w_buf[cur], acc2, og, pg, i * 8);

            // ---- (d) combine corners (now arrived) and store to nxt buffer
            if (pf) {
                float4 r;
                r.x = w00 * v00.x + w01 * v01.x + w10 * v10.x + w11 * v11.x;
                r.y = w00 * v00.y + w01 * v01.y + w10 * v10.y + w11 * v11.y;
                r.z = w00 * v00.z + w01 * v01.z + w10 * v10.z + w11 * v11.z;
                r.w = w00 * v00.w + w01 * v01.w + w10 * v10.w + w11 * v11.w;
                float* smp = smp_buf[nxt];
                smp[(cofs + 0) * SROW + wofs] = r.x;
                smp[(cofs + 1) * SROW + wofs] = r.y;
                smp[(cofs + 2) * SROW + wofs] = r.z;
                smp[(cofs + 3) * SROW + wofs] = r.w;
            }
        }

        __syncthreads();
    }

    // epilogue
    float vals[8][4];
#pragma unroll
    for (int j = 0; j < 4; j++)
#pragma unroll
        for (int p = 0; p < 4; p++)
            unpack2(acc2[j][p], vals[2 * j][p], vals[2 * j + 1][p]);

#pragma unroll
    for (int i = 0; i < 8; i++) {
        const int o = (og << 3) + i;
        const float bv = __ldg(bias + o);
        float4 r = make_float4(vals[i][0] + bv, vals[i][1] + bv,
                               vals[i][2] + bv, vals[i][3] + bv);
        *reinterpret_cast<float4*>(
            out + (((size_t)b * COUT + o) * HOUT + h) * WOUT + w_base + (pg << 2)) = r;
    }
}

extern "C" void kernel_launch(void* const* d_in, const int* in_sizes, int n_in,
                              void* d_out, int out_size)
{
    const float* x      = (const float*)d_in[0];
    const float* offset = (const float*)d_in[1];
    const float* weight = (const float*)d_in[2];
    const float* bias   = (const float*)d_in[3];
    float* out          = (float*)d_out;

    cudaFuncSetAttribute(deform_conv_kernel,
                         cudaFuncAttributeMaxDynamicSharedMemorySize, SMEM_BYTES);

    transpose_weight_kernel<<<(COUT * CIN * KK + 255) / 256, 256>>>(weight);

    dim3 gx(HW / 32, B_);
    transpose_x_kernel<<<gx, 256>>>(x);

    dim3 grid(WOUT / 64, HOUT, B_);
    deform_conv_kernel<<<grid, NTHREADS, SMEM_BYTES>>>(offset, bias, out);
}